// round 1
// baseline (speedup 1.0000x reference)
#include <cuda_runtime.h>
#include <stdint.h>

// ---------------------------------------------------------------------------
// LoraSubnet: exact top-k (k=10%) mask of |scores| with stable-sort tie-break
// by flat index, for two independent 16.7M-element fp32 matrices.
//
// Pipeline (all graph-capturable, scratch in __device__ globals):
//   1. clear          : zero histograms / state
//   2. hist1          : 8192-bin histogram of absbits[30:18] (shared-mem priv.)
//   3. select1        : find 13-bit prefix containing rank j, remainder rem1
//   4. hist2          : 262144-bin histogram of absbits[17:0] within prefix
//   5. select2        : exact threshold bits T32, tie-rank r, need_tie flag
//   6. tie_extract    : (only if need_tie) gather indices where bits==T32
//   7. tie_rank_select: idx_thresh = index of the r-th smallest tied index
//   8. mask           : out = (bits>T32) || (bits==T32 && idx>=idx_thresh)
// ---------------------------------------------------------------------------

#define H1_BITS 13
#define H1_BINS (1 << H1_BITS)     // 8192
#define H2_BITS 18
#define H2_BINS (1 << H2_BITS)     // 262144
#define TIE_CAP 16384
#define ABS_MASK 0x7fffffffu

struct SelState {
    unsigned prefix;      // selected 13-bit prefix of abs bits
    unsigned rem1;        // rank remaining within prefix group
    unsigned T32;         // exact abs-bits threshold (bits of rank-j element)
    unsigned r;           // tie-rank of rank-j element among equal-bits group
    unsigned need_tie;    // r > 0 -> must resolve by index
    unsigned idx_thresh;  // tied elems with idx >= idx_thresh get 1
};

__device__ unsigned g_hist1[2][H1_BINS];
__device__ unsigned g_hist2[2][H2_BINS];
__device__ unsigned g_tie_idx[2][TIE_CAP];
__device__ unsigned g_tie_cnt[2];
__device__ SelState g_state[2];

// ---------------------------------------------------------------------------
__global__ void clear_kernel() {
    int tid = blockIdx.x * blockDim.x + threadIdx.x;
    int total = gridDim.x * blockDim.x;
    unsigned* h2 = &g_hist2[0][0];
    for (int i = tid; i < 2 * H2_BINS; i += total) h2[i] = 0;
    unsigned* h1 = &g_hist1[0][0];
    for (int i = tid; i < 2 * H1_BINS; i += total) h1[i] = 0;
    if (tid < 2) {
        g_tie_cnt[tid] = 0;
        SelState z;
        z.prefix = 0; z.rem1 = 0; z.T32 = 0; z.r = 0; z.need_tie = 0; z.idx_thresh = 0;
        g_state[tid] = z;
    }
}

// ---------------------------------------------------------------------------
__global__ void hist1_kernel(const float4* __restrict__ A,
                             const float4* __restrict__ B, int n4) {
    __shared__ unsigned sh[H1_BINS];
    const float4* src = blockIdx.y ? B : A;
    for (int i = threadIdx.x; i < H1_BINS; i += blockDim.x) sh[i] = 0;
    __syncthreads();
    int stride = blockDim.x * gridDim.x;
    for (int i = blockIdx.x * blockDim.x + threadIdx.x; i < n4; i += stride) {
        float4 v = __ldg(src + i);
        atomicAdd(&sh[(__float_as_uint(v.x) & ABS_MASK) >> H2_BITS], 1u);
        atomicAdd(&sh[(__float_as_uint(v.y) & ABS_MASK) >> H2_BITS], 1u);
        atomicAdd(&sh[(__float_as_uint(v.z) & ABS_MASK) >> H2_BITS], 1u);
        atomicAdd(&sh[(__float_as_uint(v.w) & ABS_MASK) >> H2_BITS], 1u);
    }
    __syncthreads();
    unsigned* gh = g_hist1[blockIdx.y];
    for (int i = threadIdx.x; i < H1_BINS; i += blockDim.x) {
        unsigned c = sh[i];
        if (c) atomicAdd(&gh[i], c);
    }
}

// ---------------------------------------------------------------------------
// Single-block (1024 threads) rank-select over a histogram.
// Finds bin such that cumexcl <= rank < cumincl; returns bin and rank-cumexcl.
template <int NBINS>
__device__ bool hist_select(const unsigned* __restrict__ hist, unsigned rank,
                            unsigned& out_bin, unsigned& out_rem) {
    constexpr int PER = NBINS / 1024;
    __shared__ unsigned s[1024];
    int tid = threadIdx.x;
    int base = tid * PER;
    unsigned local = 0;
#pragma unroll 8
    for (int i = 0; i < PER; i++) local += hist[base + i];
    s[tid] = local;
    __syncthreads();
    // Hillis-Steele inclusive scan
    for (int off = 1; off < 1024; off <<= 1) {
        unsigned t = (tid >= off) ? s[tid - off] : 0u;
        __syncthreads();
        s[tid] += t;
        __syncthreads();
    }
    unsigned incl = s[tid];
    unsigned excl = incl - local;
    if (rank >= excl && rank < incl) {
        unsigned acc = excl;
        for (int i = 0; i < PER; i++) {
            unsigned c = hist[base + i];
            if (rank < acc + c) {
                out_bin = (unsigned)(base + i);
                out_rem = rank - acc;
                return true;
            }
            acc += c;
        }
    }
    return false;
}

__global__ void select1_kernel(unsigned j) {
    int m = blockIdx.x;
    unsigned bin, rem;
    if (hist_select<H1_BINS>(g_hist1[m], j, bin, rem)) {
        g_state[m].prefix = bin;
        g_state[m].rem1 = rem;
    }
}

// ---------------------------------------------------------------------------
__global__ void hist2_kernel(const float4* __restrict__ A,
                             const float4* __restrict__ B, int n4) {
    int m = blockIdx.y;
    const float4* src = m ? B : A;
    unsigned pfx = g_state[m].prefix;
    unsigned* gh = g_hist2[m];
    int stride = blockDim.x * gridDim.x;
    for (int i = blockIdx.x * blockDim.x + threadIdx.x; i < n4; i += stride) {
        float4 v = __ldg(src + i);
        unsigned b;
        b = __float_as_uint(v.x) & ABS_MASK;
        if ((b >> H2_BITS) == pfx) atomicAdd(&gh[b & (H2_BINS - 1)], 1u);
        b = __float_as_uint(v.y) & ABS_MASK;
        if ((b >> H2_BITS) == pfx) atomicAdd(&gh[b & (H2_BINS - 1)], 1u);
        b = __float_as_uint(v.z) & ABS_MASK;
        if ((b >> H2_BITS) == pfx) atomicAdd(&gh[b & (H2_BINS - 1)], 1u);
        b = __float_as_uint(v.w) & ABS_MASK;
        if ((b >> H2_BITS) == pfx) atomicAdd(&gh[b & (H2_BINS - 1)], 1u);
    }
}

__global__ void select2_kernel() {
    int m = blockIdx.x;
    unsigned rank = g_state[m].rem1;
    unsigned bin, rem;
    if (hist_select<H2_BINS>(g_hist2[m], rank, bin, rem)) {
        g_state[m].T32 = (g_state[m].prefix << H2_BITS) | bin;
        g_state[m].r = rem;
        g_state[m].need_tie = (rem > 0) ? 1u : 0u;
        g_state[m].idx_thresh = 0;  // r==0: all ties (tie-rank >= 0) get 1
    }
}

// ---------------------------------------------------------------------------
__global__ void tie_extract_kernel(const float4* __restrict__ A,
                                   const float4* __restrict__ B, int n4) {
    int m = blockIdx.y;
    if (!g_state[m].need_tie) return;
    unsigned T = g_state[m].T32;
    const float4* src = m ? B : A;
    int stride = blockDim.x * gridDim.x;
    for (int i = blockIdx.x * blockDim.x + threadIdx.x; i < n4; i += stride) {
        float4 v = __ldg(src + i);
        unsigned idx = 4u * (unsigned)i;
        if ((__float_as_uint(v.x) & ABS_MASK) == T) {
            unsigned p = atomicAdd(&g_tie_cnt[m], 1u);
            if (p < TIE_CAP) g_tie_idx[m][p] = idx + 0u;
        }
        if ((__float_as_uint(v.y) & ABS_MASK) == T) {
            unsigned p = atomicAdd(&g_tie_cnt[m], 1u);
            if (p < TIE_CAP) g_tie_idx[m][p] = idx + 1u;
        }
        if ((__float_as_uint(v.z) & ABS_MASK) == T) {
            unsigned p = atomicAdd(&g_tie_cnt[m], 1u);
            if (p < TIE_CAP) g_tie_idx[m][p] = idx + 2u;
        }
        if ((__float_as_uint(v.w) & ABS_MASK) == T) {
            unsigned p = atomicAdd(&g_tie_cnt[m], 1u);
            if (p < TIE_CAP) g_tie_idx[m][p] = idx + 3u;
        }
    }
}

// idx_thresh = the tied index with exactly r smaller tied indices.
// Tie counts are tiny (typically < 32); O(c^2) rank is trivial.
__global__ void tie_rank_select_kernel() {
    int m = blockIdx.x;
    if (!g_state[m].need_tie) return;
    unsigned tc = g_tie_cnt[m];
    if (tc > TIE_CAP) tc = TIE_CAP;
    unsigned r = g_state[m].r;
    for (unsigned e = threadIdx.x; e < tc; e += blockDim.x) {
        unsigned my = g_tie_idx[m][e];
        unsigned rank = 0;
        for (unsigned k = 0; k < tc; k++) rank += (g_tie_idx[m][k] < my) ? 1u : 0u;
        if (rank == r) g_state[m].idx_thresh = my;
    }
}

// ---------------------------------------------------------------------------
__device__ __forceinline__ float keep(unsigned b, unsigned idx, unsigned T,
                                      unsigned it) {
    return (b > T || (b == T && idx >= it)) ? 1.0f : 0.0f;
}

__global__ void mask_kernel(const float4* __restrict__ A,
                            const float4* __restrict__ B,
                            float4* __restrict__ out, int n4) {
    int m = blockIdx.y;
    const float4* src = m ? B : A;
    float4* dst = out + (size_t)m * (size_t)n4;
    unsigned T = g_state[m].T32;
    unsigned it = g_state[m].idx_thresh;
    int stride = blockDim.x * gridDim.x;
    for (int i = blockIdx.x * blockDim.x + threadIdx.x; i < n4; i += stride) {
        float4 v = __ldg(src + i);
        unsigned idx = 4u * (unsigned)i;
        float4 o;
        o.x = keep(__float_as_uint(v.x) & ABS_MASK, idx + 0u, T, it);
        o.y = keep(__float_as_uint(v.y) & ABS_MASK, idx + 1u, T, it);
        o.z = keep(__float_as_uint(v.z) & ABS_MASK, idx + 2u, T, it);
        o.w = keep(__float_as_uint(v.w) & ABS_MASK, idx + 3u, T, it);
        dst[i] = o;
    }
}

// ---------------------------------------------------------------------------
extern "C" void kernel_launch(void* const* d_in, const int* in_sizes, int n_in,
                              void* d_out, int out_size) {
    const float4* A = (const float4*)d_in[0];
    const float4* B = (const float4*)d_in[1];
    float4* out = (float4*)d_out;

    unsigned n = (unsigned)in_sizes[0];     // 16,777,216 per matrix
    int n4 = (int)(n / 4u);
    // Mirror Python int((1.0 - 0.1) * n) exactly (double arithmetic, truncate)
    unsigned j = (unsigned)((1.0 - 0.1) * (double)n);

    clear_kernel<<<2048, 256>>>();

    dim3 g1(296, 2);
    hist1_kernel<<<g1, 512>>>(A, B, n4);

    select1_kernel<<<2, 1024>>>(j);

    dim3 g2(1184, 2);
    hist2_kernel<<<g2, 256>>>(A, B, n4);

    select2_kernel<<<2, 1024>>>();

    tie_extract_kernel<<<g2, 256>>>(A, B, n4);
    tie_rank_select_kernel<<<2, 256>>>();

    dim3 gm(1184, 2);
    mask_kernel<<<gm, 256>>>(A, B, out, n4);
}